// round 1
// baseline (speedup 1.0000x reference)
#include <cuda_runtime.h>
#include <cstdint>

#define HIN 512
#define WIN 512
#define NP  724
#define NA  180
#define PAD 106
#define CENTER 361.5f
#define PI_D 3.14159265358979323846

__device__ float g_cos[NA];
__device__ float g_sin[NA];

__global__ void setup_angles_kernel() {
    int i = threadIdx.x;
    if (i < NA) {
        // angles_deg = linspace(0,180,180): step 180/179 deg -> i * pi/179 rad
        double ang = (double)i * (PI_D / 179.0);
        g_cos[i] = (float)cos(ang);
        g_sin[i] = (float)sin(ang);
    }
}

__global__ __launch_bounds__(192) void radon_kernel(
    const float* __restrict__ img,   // [512,512]
    float* __restrict__ sino,        // [180,724]
    float* __restrict__ rot)         // [180,724,724]
{
    const int y = blockIdx.x;   // output row within rotated frame
    const int n = blockIdx.y;   // angle
    const int t = threadIdx.x;

    const float c = g_cos[n];
    const float s = g_sin[n];
    const float v = (float)y - CENTER;
    // per-row constants: ix = c*u + ixr ; iy = s*u + iyr  (u = x - CENTER)
    const float ixr = fmaf(-s, v, CENTER);
    const float iyr = fmaf( c, v, CENTER);

    float sum = 0.0f;

    if (t < NP / 4) {  // 181 active threads, 4 consecutive x each
        const int xb = t * 4;
        float res[4];
#pragma unroll
        for (int k = 0; k < 4; k++) {
            const float u  = (float)(xb + k) - CENTER;
            const float ix = fmaf(c, u, ixr);
            const float iy = fmaf(s, u, iyr);
            const float xf = floorf(ix);
            const float yf = floorf(iy);
            const float wx = ix - xf;
            const float wy = iy - yf;
            // shift from padded coords into input coords
            const int x0 = (int)xf - PAD;
            const int y0 = (int)yf - PAD;

            float a00 = 0.f, a01 = 0.f, a10 = 0.f, a11 = 0.f;
            const bool X0 = ((unsigned)x0       < (unsigned)WIN);
            const bool X1 = ((unsigned)(x0 + 1) < (unsigned)WIN);
            const bool Y0 = ((unsigned)y0       < (unsigned)HIN);
            const bool Y1 = ((unsigned)(y0 + 1) < (unsigned)HIN);
            const float* r0 = img + (long long)y0 * WIN;
            if (Y0) {
                if (X0) a00 = __ldg(r0 + x0);
                if (X1) a01 = __ldg(r0 + x0 + 1);
            }
            if (Y1) {
                if (X0) a10 = __ldg(r0 + WIN + x0);
                if (X1) a11 = __ldg(r0 + WIN + x0 + 1);
            }
            const float top = fmaf(wx, a01 - a00, a00);
            const float bot = fmaf(wx, a11 - a10, a10);
            const float r   = fmaf(wy, bot - top, top);
            res[k] = r;
            sum += r;
        }
        float4* dst = reinterpret_cast<float4*>(rot + ((size_t)n * NP + y) * NP) + t;
        *dst = make_float4(res[0], res[1], res[2], res[3]);
    }

    // block reduction of row sum -> sinogram[n, y]
#pragma unroll
    for (int o = 16; o > 0; o >>= 1)
        sum += __shfl_down_sync(0xffffffffu, sum, o);
    __shared__ float ws[6];
    if ((t & 31) == 0) ws[t >> 5] = sum;
    __syncthreads();
    if (t == 0) {
        float tot = 0.f;
#pragma unroll
        for (int i = 0; i < 6; i++) tot += ws[i];
        sino[(size_t)n * NP + y] = tot;
    }
}

extern "C" void kernel_launch(void* const* d_in, const int* in_sizes, int n_in,
                              void* d_out, int out_size) {
    const float* x = (const float*)d_in[0];
    float* sino = (float*)d_out;                 // [180,724]
    float* rot  = sino + (size_t)NA * NP;        // [180,1,724,724]

    setup_angles_kernel<<<1, 192>>>();
    dim3 grid(NP, NA);
    radon_kernel<<<grid, 192>>>(x, sino, rot);
}

// round 2
// speedup vs baseline: 1.3100x; 1.3100x over previous
#include <cuda_runtime.h>
#include <cstdint>

#define HIN 512
#define WIN 512
#define NP  724
#define NA  180
#define PAD 106
#define CENTER 361.5f
#define PI_D 3.14159265358979323846

__device__ float g_cos[NA];
__device__ float g_sin[NA];
__device__ float g_imgT[HIN * WIN];   // transposed copy of the input

__global__ void setup_angles_kernel() {
    int i = threadIdx.x;
    if (i < NA) {
        // angles_deg = linspace(0,180,180): step = 180/179 deg -> i * pi/179 rad
        double ang = (double)i * (PI_D / 179.0);
        g_cos[i] = (float)cos(ang);
        g_sin[i] = (float)sin(ang);
    }
}

__global__ __launch_bounds__(256) void transpose_kernel(const float* __restrict__ img) {
    __shared__ float tile[32][33];
    const int bx = blockIdx.x * 32;
    const int by = blockIdx.y * 32;
    const int tx = threadIdx.x & 31;
    const int ty = threadIdx.x >> 5;   // 0..7
#pragma unroll
    for (int r = 0; r < 32; r += 8)
        tile[ty + r][tx] = img[(size_t)(by + ty + r) * WIN + bx + tx];
    __syncthreads();
#pragma unroll
    for (int r = 0; r < 32; r += 8)
        g_imgT[(size_t)(bx + ty + r) * HIN + by + tx] = tile[tx][ty + r];
}

__global__ __launch_bounds__(256) void radon_kernel(
    const float* __restrict__ img,   // [512,512]
    float* __restrict__ sino,        // [180,724]
    float* __restrict__ rot)         // [180,724,724]
{
    const int y = blockIdx.x;   // output row within rotated frame
    const int n = blockIdx.y;   // angle
    const int t = threadIdx.x;

    const float c = g_cos[n];
    const float s = g_sin[n];
    const float v = (float)y - CENTER;
    // ix = c*u + ixr ; iy = s*u + iyr   (u = x - CENTER)
    const float ixr = fmaf(-s, v, CENTER);
    const float iyr = fmaf( c, v, CENTER);

    // steep: gather from the transposed image so warp lanes stay row-compact
    const bool steep = fabsf(s) > fabsf(c);
    const float* __restrict__ base = steep ? g_imgT : img;
    const int strideX = steep ? WIN : 1;   // step when x-corner increments
    const int strideY = steep ? 1 : WIN;   // step when y-corner increments

    float* __restrict__ rowOut = rot + ((size_t)n * NP + y) * NP;

    float sum = 0.0f;

#pragma unroll
    for (int k = 0; k < 3; k++) {
        const int x = t + k * 256;
        if (x < NP) {
            const float u  = (float)x - CENTER;
            const float ix = fmaf(c, u, ixr);
            const float iy = fmaf(s, u, iyr);
            const float xf = floorf(ix);
            const float yf = floorf(iy);
            const float wx = ix - xf;
            const float wy = iy - yf;
            const int x0 = (int)xf - PAD;   // input coords
            const int y0 = (int)yf - PAD;

            float a00 = 0.f, a01 = 0.f, a10 = 0.f, a11 = 0.f;
            const bool X0 = ((unsigned)x0       < (unsigned)WIN);
            const bool X1 = ((unsigned)(x0 + 1) < (unsigned)WIN);
            const bool Y0 = ((unsigned)y0       < (unsigned)HIN);
            const bool Y1 = ((unsigned)(y0 + 1) < (unsigned)HIN);
            const float* p = base + (long long)x0 * strideX + (long long)y0 * strideY;
            if (Y0) {
                if (X0) a00 = __ldg(p);
                if (X1) a01 = __ldg(p + strideX);
            }
            if (Y1) {
                if (X0) a10 = __ldg(p + strideY);
                if (X1) a11 = __ldg(p + strideX + strideY);
            }
            const float top = fmaf(wx, a01 - a00, a00);
            const float bot = fmaf(wx, a11 - a10, a10);
            const float r   = fmaf(wy, bot - top, top);
            rowOut[x] = r;
            sum += r;
        }
    }

    // block reduction of row sum -> sinogram[n, y]
#pragma unroll
    for (int o = 16; o > 0; o >>= 1)
        sum += __shfl_down_sync(0xffffffffu, sum, o);
    __shared__ float ws[8];
    if ((t & 31) == 0) ws[t >> 5] = sum;
    __syncthreads();
    if (t == 0) {
        float tot = 0.f;
#pragma unroll
        for (int i = 0; i < 8; i++) tot += ws[i];
        sino[(size_t)n * NP + y] = tot;
    }
}

extern "C" void kernel_launch(void* const* d_in, const int* in_sizes, int n_in,
                              void* d_out, int out_size) {
    const float* x = (const float*)d_in[0];
    float* sino = (float*)d_out;                 // [180,724]
    float* rot  = sino + (size_t)NA * NP;        // [180,1,724,724]

    setup_angles_kernel<<<1, 192>>>();
    transpose_kernel<<<dim3(WIN / 32, HIN / 32), 256>>>(x);
    dim3 grid(NP, NA);
    radon_kernel<<<grid, 256>>>(x, sino, rot);
}

// round 4
// speedup vs baseline: 1.3566x; 1.0355x over previous
#include <cuda_runtime.h>
#include <cstdint>

#define HIN 512
#define WIN 512
#define NP  724
#define NA  180
#define PAD 106
#define CENTER 361.5f
#define PI_D 3.14159265358979323846

// Pair images: gpairN[y*512+x] = (img[y][x], img[y+1][x])   (row y=511 pairs with 0)
//              gpairT[x*512+y] = (img[y][x], img[y][x+1])   (col x=511 pairs with 0)
__device__ float2 g_pairN[HIN * WIN];
__device__ float2 g_pairT[HIN * WIN];

__global__ __launch_bounds__(256) void prep_kernel(const float* __restrict__ img) {
    __shared__ float tile[33][34];
    const int bx = blockIdx.x * 32;
    const int by = blockIdx.y * 32;
    // load 33x33 halo tile (zero outside image)
    for (int idx = threadIdx.x; idx < 33 * 33; idx += 256) {
        const int r = idx / 33, c = idx % 33;
        const int gy = by + r, gx = bx + c;
        float v = 0.f;
        if (gy < HIN && gx < WIN) v = img[gy * WIN + gx];
        tile[r][c] = v;
    }
    __syncthreads();
    const int tx = threadIdx.x & 31;
    const int tg = threadIdx.x >> 5;   // 0..7
#pragma unroll
    for (int r = tg; r < 32; r += 8)
        g_pairN[(size_t)(by + r) * WIN + bx + tx] =
            make_float2(tile[r][tx], tile[r + 1][tx]);
#pragma unroll
    for (int c = tg; c < 32; c += 8)
        g_pairT[(size_t)(bx + c) * HIN + by + tx] =
            make_float2(tile[tx][c], tile[tx][c + 1]);
}

__global__ __launch_bounds__(256) void radon_kernel(
    float* __restrict__ sino,        // [180,724]
    float* __restrict__ rot)         // [180,724,724]
{
    const int y = blockIdx.x;   // output row within rotated frame
    const int n = blockIdx.y;   // angle
    const int t = threadIdx.x;

    // angles = linspace(0,180,180) deg -> step = pi/179 rad
    float s, c;
    sincosf((float)n * (float)(PI_D / 179.0), &s, &c);

    const float v = (float)y - CENTER;
    // ix = c*u + ixr ; iy = s*u + iyr   (u = x - CENTER)
    const float ixr = fmaf(-s, v, CENTER);
    const float iyr = fmaf( c, v, CENTER);

    // steep: warp-compact dimension is the image row index -> use transposed pairs
    const bool steep = fabsf(s) > fabsf(c);
    const float2* __restrict__ buf = steep ? g_pairT : g_pairN;

    float* __restrict__ rowOut = rot + ((size_t)n * NP + y) * NP;

    float sum = 0.0f;

#pragma unroll
    for (int k = 0; k < 3; k++) {
        const int x = t + k * 256;
        if (x < NP) {
            const float u  = (float)x - CENTER;
            const float ix = fmaf(c, u, ixr);
            const float iy = fmaf(s, u, iyr);
            const float xf = floorf(ix);
            const float yf = floorf(iy);
            const float wx = ix - xf;
            const float wy = iy - yf;
            const int x0 = (int)xf - PAD;   // input coords
            const int y0 = (int)yf - PAD;

            // unify: i = compact dim, j = pair dim
            const int   i  = steep ? y0 : x0;
            const int   j  = steep ? x0 : y0;
            const float wi = steep ? wy : wx;
            const float wj = steep ? wx : wy;

            float2 v0 = make_float2(0.f, 0.f);
            float2 v1 = make_float2(0.f, 0.f);
            const bool jwin = ((unsigned)(j + 1) <= (unsigned)HIN);  // j in [-1,511]
            if (jwin) {
                const float2* row = buf + (size_t)max(j, 0) * WIN;
                if ((unsigned)i       < (unsigned)WIN) v0 = __ldg(row + i);
                if ((unsigned)(i + 1) < (unsigned)WIN) v1 = __ldg(row + i + 1);
            }
            const bool jn = (j >= 0);
            // corners: A=a(j,i) B=a(j,i+1) C=a(j+1,i) D=a(j+1,i+1)
            const float A = jn ? v0.x : 0.f;
            const float C = jn ? v0.y : v0.x;
            const float B = jn ? v1.x : 0.f;
            const float D = jn ? v1.y : v1.x;

            const float top = fmaf(wi, B - A, A);
            const float bot = fmaf(wi, D - C, C);
            const float r   = fmaf(wj, bot - top, top);
            rowOut[x] = r;
            sum += r;
        }
    }

    // block reduction of row sum -> sinogram[n, y]
#pragma unroll
    for (int o = 16; o > 0; o >>= 1)
        sum += __shfl_down_sync(0xffffffffu, sum, o);
    __shared__ float ws[8];
    if ((t & 31) == 0) ws[t >> 5] = sum;
    __syncthreads();
    if (t == 0) {
        float tot = 0.f;
#pragma unroll
        for (int i = 0; i < 8; i++) tot += ws[i];
        sino[(size_t)n * NP + y] = tot;
    }
}

extern "C" void kernel_launch(void* const* d_in, const int* in_sizes, int n_in,
                              void* d_out, int out_size) {
    const float* x = (const float*)d_in[0];
    float* sino = (float*)d_out;                 // [180,724]
    float* rot  = sino + (size_t)NA * NP;        // [180,1,724,724]

    prep_kernel<<<dim3(WIN / 32, HIN / 32), 256>>>(x);
    dim3 grid(NP, NA);
    radon_kernel<<<grid, 256>>>(sino, rot);
}